// round 1
// baseline (speedup 1.0000x reference)
#include <cuda_runtime.h>
#include <math.h>

#define T_LEN   2048
#define B_SZ    4
#define DMODEL  1024
#define DINNER  2048
#define DSTATE  16
#define DTRANK  64
#define NXP     96
#define M_ROWS  (B_SZ*T_LEN)   // 8192
#define DPROJ   (2*DINNER)     // 4096

// ---------------- scratch (device globals; no runtime allocation) ----------------
__device__ __align__(16) float g_P[(size_t)M_ROWS * DPROJ];     // in_proj output (u | res)
__device__ __align__(16) float g_uc[(size_t)M_ROWS * DINNER];   // conv+silu output
__device__ __align__(16) float g_xdbl[(size_t)M_ROWS * NXP];    // x_proj output (dt|B|C)
__device__ __align__(16) float g_delta[(size_t)M_ROWS * DINNER];// softplus(dt_proj)
__device__ __align__(16) float g_y[(size_t)M_ROWS * DINNER];    // gated ssm output

// =================================================================================
// Generic fp32 GEMM: C[M,N] = A[M,K] @ B[K,N]
// MODE 0: A = x with (t,b,c) row mapping (m = b*T + t), C = g_P
// MODE 1: A = g_y (plain row-major), C = param, written with (t,b,c) mapping
// Tiles: 128x128x16, 256 threads, 8x8 microtile, double-buffered SMEM.
// =================================================================================
__device__ __forceinline__ size_t map_tbc(int m, int col) {
    // row m = b*T + t  ->  offset t*(B*DMODEL) + b*DMODEL + col
    return (size_t)(m & (T_LEN - 1)) * (B_SZ * DMODEL) + (size_t)(m >> 11) * DMODEL + col;
}

template<int MODE>
__global__ __launch_bounds__(256, 2)
void gemm_f32(const float* __restrict__ Aparam, const float* __restrict__ Bw,
              float* __restrict__ Cparam, int M, int N, int K)
{
    __shared__ float As[2][16][128];
    __shared__ float Bs[2][16][128];

    const float* A = (MODE == 1) ? g_y : Aparam;
    float*       C = (MODE == 1) ? Cparam : g_P;

    const int tid = threadIdx.x;
    const int bm = blockIdx.y * 128;
    const int bn = blockIdx.x * 128;

    const int ar = tid >> 2;          // 0..63
    const int ac = (tid & 3) << 2;    // 0,4,8,12
    const int br = tid >> 5;          // 0..7
    const int bc = (tid & 31) << 2;   // 0..124
    const int tx = tid & 15;
    const int ty = tid >> 4;

    float acc[8][8];
    #pragma unroll
    for (int i = 0; i < 8; i++)
        #pragma unroll
        for (int j = 0; j < 8; j++) acc[i][j] = 0.f;

    float4 pa0, pa1, pb0, pb1;

    // ---- load tile 0 ----
    {
        size_t o0 = (MODE == 0) ? map_tbc(bm + ar, ac)      : (size_t)(bm + ar) * K + ac;
        size_t o1 = (MODE == 0) ? map_tbc(bm + ar + 64, ac) : (size_t)(bm + ar + 64) * K + ac;
        pa0 = *(const float4*)(A + o0);
        pa1 = *(const float4*)(A + o1);
        pb0 = *(const float4*)(Bw + (size_t)br * N + bn + bc);
        pb1 = *(const float4*)(Bw + (size_t)(br + 8) * N + bn + bc);
    }
    As[0][ac + 0][ar] = pa0.x; As[0][ac + 1][ar] = pa0.y;
    As[0][ac + 2][ar] = pa0.z; As[0][ac + 3][ar] = pa0.w;
    As[0][ac + 0][ar + 64] = pa1.x; As[0][ac + 1][ar + 64] = pa1.y;
    As[0][ac + 2][ar + 64] = pa1.z; As[0][ac + 3][ar + 64] = pa1.w;
    *(float4*)&Bs[0][br][bc]     = pb0;
    *(float4*)&Bs[0][br + 8][bc] = pb1;
    __syncthreads();

    const int KT = K >> 4;
    for (int kt = 0; kt < KT; kt++) {
        const int s = kt & 1;
        if (kt + 1 < KT) {
            const int k0 = (kt + 1) << 4;
            size_t o0 = (MODE == 0) ? map_tbc(bm + ar, k0 + ac)      : (size_t)(bm + ar) * K + k0 + ac;
            size_t o1 = (MODE == 0) ? map_tbc(bm + ar + 64, k0 + ac) : (size_t)(bm + ar + 64) * K + k0 + ac;
            pa0 = *(const float4*)(A + o0);
            pa1 = *(const float4*)(A + o1);
            pb0 = *(const float4*)(Bw + (size_t)(k0 + br) * N + bn + bc);
            pb1 = *(const float4*)(Bw + (size_t)(k0 + br + 8) * N + bn + bc);
        }
        #pragma unroll
        for (int k = 0; k < 16; k++) {
            float a[8], bf[8];
            *(float4*)&a[0]  = *(const float4*)&As[s][k][ty * 8];
            *(float4*)&a[4]  = *(const float4*)&As[s][k][ty * 8 + 4];
            *(float4*)&bf[0] = *(const float4*)&Bs[s][k][tx * 8];
            *(float4*)&bf[4] = *(const float4*)&Bs[s][k][tx * 8 + 4];
            #pragma unroll
            for (int i = 0; i < 8; i++)
                #pragma unroll
                for (int j = 0; j < 8; j++)
                    acc[i][j] = fmaf(a[i], bf[j], acc[i][j]);
        }
        if (kt + 1 < KT) {
            const int ss = s ^ 1;
            As[ss][ac + 0][ar] = pa0.x; As[ss][ac + 1][ar] = pa0.y;
            As[ss][ac + 2][ar] = pa0.z; As[ss][ac + 3][ar] = pa0.w;
            As[ss][ac + 0][ar + 64] = pa1.x; As[ss][ac + 1][ar + 64] = pa1.y;
            As[ss][ac + 2][ar + 64] = pa1.z; As[ss][ac + 3][ar + 64] = pa1.w;
            *(float4*)&Bs[ss][br][bc]     = pb0;
            *(float4*)&Bs[ss][br + 8][bc] = pb1;
        }
        __syncthreads();
    }

    #pragma unroll
    for (int i = 0; i < 8; i++) {
        const int row = bm + ty * 8 + i;
        const int col = bn + tx * 8;
        size_t off = (MODE == 1) ? map_tbc(row, col) : (size_t)row * N + col;
        float4 v0 = make_float4(acc[i][0], acc[i][1], acc[i][2], acc[i][3]);
        float4 v1 = make_float4(acc[i][4], acc[i][5], acc[i][6], acc[i][7]);
        *(float4*)(C + off)     = v0;
        *(float4*)(C + off + 4) = v1;
    }
}

// =================================================================================
// Depthwise causal conv (k=4) + bias + silu.  u = P[:, :DINNER]
// =================================================================================
__global__ __launch_bounds__(256)
void conv_silu_kernel(const float* __restrict__ cw, const float* __restrict__ cb)
{
    const int idx = blockIdx.x * 256 + threadIdx.x;   // m*DINNER + d
    const int d = idx & (DINNER - 1);
    const int m = idx >> 11;
    const int t = m & (T_LEN - 1);
    const int b = m >> 11;

    const float4 w = *(const float4*)(cw + d * 4);
    float acc = cb[d];
    const size_t rowbase = (size_t)(b * T_LEN) * DPROJ + d;
    if (t >= 3) acc = fmaf(g_P[rowbase + (size_t)(t - 3) * DPROJ], w.x, acc);
    if (t >= 2) acc = fmaf(g_P[rowbase + (size_t)(t - 2) * DPROJ], w.y, acc);
    if (t >= 1) acc = fmaf(g_P[rowbase + (size_t)(t - 1) * DPROJ], w.z, acc);
    acc = fmaf(g_P[rowbase + (size_t)t * DPROJ], w.w, acc);
    // silu
    acc = acc * (1.f / (1.f + __expf(-acc)));
    g_uc[idx] = acc;
}

// =================================================================================
// x_proj: xdbl[m, 0:96] = uc[m, :] @ W_x   (K=2048, N=96)
// Block = 16 m-rows, 128 threads (96 compute, all load). K chunked by 64 via SMEM.
// =================================================================================
__global__ __launch_bounds__(128)
void xproj_kernel(const float* __restrict__ W_x)
{
    __shared__ float swl[64 * 96];   // W_x chunk [64 k][96 j], row-major contiguous
    __shared__ float su[16][64];     // uc chunk
    const int m0 = blockIdx.x * 16;
    const int tid = threadIdx.x;

    float acc[16];
    #pragma unroll
    for (int mi = 0; mi < 16; mi++) acc[mi] = 0.f;

    for (int kb = 0; kb < DINNER; kb += 64) {
        __syncthreads();
        #pragma unroll 4
        for (int i = tid; i < 64 * 96; i += 128) swl[i] = W_x[kb * 96 + i];
        #pragma unroll
        for (int i = tid; i < 16 * 64; i += 128) {
            const int mi = i >> 6, c = i & 63;
            su[mi][c] = g_uc[(size_t)(m0 + mi) * DINNER + kb + c];
        }
        __syncthreads();
        if (tid < 96) {
            #pragma unroll 2
            for (int r = 0; r < 64; r++) {
                const float w = swl[r * 96 + tid];
                #pragma unroll
                for (int mi = 0; mi < 16; mi++)
                    acc[mi] = fmaf(su[mi][r], w, acc[mi]);
            }
        }
    }
    if (tid < 96) {
        #pragma unroll
        for (int mi = 0; mi < 16; mi++)
            g_xdbl[(size_t)(m0 + mi) * NXP + tid] = acc[mi];
    }
}

// =================================================================================
// dt_proj + softplus: delta[m,d] = softplus(xdbl[m,0:64] @ W_dt[:,d] + b_dt[d])
// Block = 16 m-rows x 128 d-cols.
// =================================================================================
__global__ __launch_bounds__(128)
void dtproj_kernel(const float* __restrict__ W_dt, const float* __restrict__ b_dt)
{
    __shared__ float sw[64][128];
    __shared__ float sx[16][64];
    const int d0 = blockIdx.x * 128;
    const int m0 = blockIdx.y * 16;
    const int tid = threadIdx.x;

    #pragma unroll 4
    for (int i = tid; i < 64 * 128; i += 128) {
        const int r = i >> 7, dd = i & 127;
        sw[r][dd] = W_dt[(size_t)r * DINNER + d0 + dd];
    }
    #pragma unroll
    for (int i = tid; i < 16 * 64; i += 128) {
        const int mi = i >> 6, r = i & 63;
        sx[mi][r] = g_xdbl[(size_t)(m0 + mi) * NXP + r];
    }
    __syncthreads();

    float acc[16];
    const float bb = b_dt[d0 + tid];
    #pragma unroll
    for (int mi = 0; mi < 16; mi++) acc[mi] = bb;

    #pragma unroll 2
    for (int r = 0; r < 64; r++) {
        const float w = sw[r][tid];
        #pragma unroll
        for (int mi = 0; mi < 16; mi++)
            acc[mi] = fmaf(sx[mi][r], w, acc[mi]);
    }
    #pragma unroll
    for (int mi = 0; mi < 16; mi++) {
        const float z = acc[mi];
        const float sp = (z > 15.f) ? z : log1pf(__expf(z));
        g_delta[(size_t)(m0 + mi) * DINNER + d0 + tid] = sp;
    }
}

// =================================================================================
// Selective scan + skip + gate.
// Lane layout: 4 states per lane, 4 lanes per d-channel, 8 d-channels per warp.
// Block = 128 threads = 32 d-channels. Grid = (DINNER/32, B).
// =================================================================================
__global__ __launch_bounds__(128)
void scan_kernel(const float* __restrict__ A_log, const float* __restrict__ Dv)
{
    const int b = blockIdx.y;
    const int d0 = blockIdx.x * 32;
    const int tid = threadIdx.x;
    const int w = tid >> 5, lane = tid & 31;
    const int g = lane >> 2, q = lane & 3;
    const int d = d0 + w * 8 + g;
    const int nb = q * 4;

    const float A0 = -__expf(A_log[d * DSTATE + nb + 0]);
    const float A1 = -__expf(A_log[d * DSTATE + nb + 1]);
    const float A2 = -__expf(A_log[d * DSTATE + nb + 2]);
    const float A3 = -__expf(A_log[d * DSTATE + nb + 3]);
    const float Dd = Dv[d];

    float h0 = 0.f, h1 = 0.f, h2 = 0.f, h3 = 0.f;
    size_t base  = (size_t)b * T_LEN * DINNER + d;
    size_t rbase = (size_t)b * T_LEN * DPROJ + DINNER + d;
    size_t xb    = (size_t)b * T_LEN * NXP;

    #pragma unroll 2
    for (int t = 0; t < T_LEN; t++) {
        const float dl = g_delta[base];
        const float uu = g_uc[base];
        const float4 Bv = *(const float4*)&g_xdbl[xb + DTRANK + nb];
        const float4 Cv = *(const float4*)&g_xdbl[xb + DTRANK + DSTATE + nb];

        const float du = dl * uu;
        h0 = fmaf(__expf(dl * A0), h0, du * Bv.x);
        h1 = fmaf(__expf(dl * A1), h1, du * Bv.y);
        h2 = fmaf(__expf(dl * A2), h2, du * Bv.z);
        h3 = fmaf(__expf(dl * A3), h3, du * Bv.w);

        float p = fmaf(h0, Cv.x, fmaf(h1, Cv.y, fmaf(h2, Cv.z, h3 * Cv.w)));
        p += __shfl_xor_sync(0xffffffffu, p, 1);
        p += __shfl_xor_sync(0xffffffffu, p, 2);

        if (q == 0) {
            const float resv = g_P[rbase];
            const float gate = resv * (1.f / (1.f + __expf(-resv)));
            g_y[base] = (p + uu * Dd) * gate;
        }
        base += DINNER;
        rbase += DPROJ;
        xb += NXP;
    }
}

// =================================================================================
// launch
// =================================================================================
extern "C" void kernel_launch(void* const* d_in, const int* in_sizes, int n_in,
                              void* d_out, int out_size)
{
    const float* x      = (const float*)d_in[0];
    const float* W_in   = (const float*)d_in[1];
    const float* conv_w = (const float*)d_in[2];
    const float* conv_b = (const float*)d_in[3];
    const float* W_x    = (const float*)d_in[4];
    const float* W_dt   = (const float*)d_in[5];
    const float* b_dt   = (const float*)d_in[6];
    const float* A_log  = (const float*)d_in[7];
    const float* Dv     = (const float*)d_in[8];
    const float* W_out  = (const float*)d_in[9];
    float* out = (float*)d_out;

    // 1) in_proj: g_P[8192,4096] = x(mapped) @ W_in
    gemm_f32<0><<<dim3(DPROJ / 128, M_ROWS / 128), 256>>>(x, W_in, nullptr, M_ROWS, DPROJ, DMODEL);

    // 2) depthwise conv + silu -> g_uc
    conv_silu_kernel<<<(M_ROWS * DINNER) / 256, 256>>>(conv_w, conv_b);

    // 3) x_proj -> g_xdbl[8192,96]
    xproj_kernel<<<M_ROWS / 16, 128>>>(W_x);

    // 4) dt_proj + softplus -> g_delta
    dtproj_kernel<<<dim3(DINNER / 128, M_ROWS / 16), 128>>>(W_dt, b_dt);

    // 5) selective scan + skip + gate -> g_y
    scan_kernel<<<dim3(DINNER / 32, B_SZ), 128>>>(A_log, Dv);

    // 6) out_proj: out(t,b,c) = g_y @ W_out
    gemm_f32<1><<<dim3(DMODEL / 128, M_ROWS / 128), 256>>>(nullptr, W_out, out, M_ROWS, DMODEL, DINNER);
}